// round 15
// baseline (speedup 1.0000x reference)
#include <cuda_runtime.h>
#include <cstdint>

#define B 32
#define M 32
#define C 1024
#define R 28
#define INV_R2 (1.0f / (R * R))

#define IMGS 8
#define ROWS (IMGS * R)                  // 224
#define TILE_FLOATS (ROWS * R)           // 6272
#define TILE_BYTES (TILE_FLOATS * 4)     // 25088
#define THREADS 288                      // 8 consumer warps + 1 producer warp
#define NCONS 256
#define BLKS_PER_B (C / IMGS)            // 128
#define NTILES (B * C / IMGS)            // 4096
#define GRID 592                         // 4 blocks/SM x 148

// Dynamic smem layout (bytes)
#define OFF_T0    0
#define OFF_T1    TILE_BYTES             // 25088
#define OFF_COL   (2 * TILE_BYTES)       // 50176 : col_s, 896 floats
#define OFF_ROW   (OFF_COL + 3584)       // 53760 : rowsum, 224 floats
#define OFF_MBAR  (OFF_ROW + 896)        // 54656 : full[2], empty[2]
#define SMEM_TOTAL (OFF_MBAR + 32)       // 54688  -> 4 blocks/SM

__device__ float g_col[B * M * R];

__device__ __forceinline__ uint32_t smem_u32(const void* p) {
    uint32_t a;
    asm("{ .reg .u64 t; cvta.to.shared.u64 t, %1; cvt.u32.u64 %0, t; }"
        : "=r"(a) : "l"(p));
    return a;
}

__device__ __forceinline__ void mbar_wait(uint32_t mbar_a, uint32_t parity) {
    uint32_t done;
    asm volatile(
        "{\n\t.reg .pred p;\n\t"
        "mbarrier.try_wait.parity.acquire.cta.shared::cta.b64 p, [%1], %2;\n\t"
        "selp.b32 %0, 1, 0, p;\n\t}"
        : "=r"(done) : "r"(mbar_a), "r"(parity) : "memory");
    if (!done) {
        asm volatile(
            "{\n\t.reg .pred P1;\n\t"
            "WL_%=:\n\t"
            "mbarrier.try_wait.parity.acquire.cta.shared::cta.b64 P1, [%0], %1, 0x989680;\n\t"
            "@P1 bra.uni WD_%=;\n\t"
            "bra.uni WL_%=;\n\t"
            "WD_%=:\n\t}"
            :: "r"(mbar_a), "r"(parity) : "memory");
    }
}

// ---------------------------------------------------------------------------
// Kernel 1 (primary): col[b,m,j] = sum_i Masks[b,m,i,j]. PDL-trigger first.
// ---------------------------------------------------------------------------
__global__ void reduce_M_kernel(const float* __restrict__ Mk) {
    cudaTriggerProgrammaticLaunchCompletion();
    int tid = blockIdx.x * blockDim.x + threadIdx.x;
    if (tid >= B * M * R) return;
    int j  = tid % R;
    int bm = tid / R;
    const float* p = Mk + (size_t)bm * R * R + j;
    float s = 0.0f;
#pragma unroll
    for (int i = 0; i < R; i++) s += __ldcs(p + i * R);
    g_col[tid] = s;
}

// ---------------------------------------------------------------------------
// Kernel 2 (secondary, PDL): PERSISTENT + WARP-SPECIALIZED TMA PIPELINE.
// Warp 8 (producer): waits empty[s], issues expect_tx + cp.async.bulk —
// back-to-back, never touching consumer barriers. Warps 0-7 (256 consumers):
// stage col -> wait full[s] -> rowsum (t<224) -> named bar -> arrive
// empty[s] -> einsum (1 output/thread, 4-way split acc chain) -> named bar.
// Copies are issue-decoupled from compute, killing the per-iteration
// max(copy, compute) coupling that left the TMA engine idle 37% in R14.
// ---------------------------------------------------------------------------
__global__ void __launch_bounds__(THREADS, 4)
persistent_fused_kernel(const float* __restrict__ F, float* __restrict__ out) {
    extern __shared__ char smem[];
    float* tiles[2] = { (float*)(smem + OFF_T0), (float*)(smem + OFF_T1) };
    float* col_s    = (float*)(smem + OFF_COL);   // [m*28 + r]
    float* rowsum   = (float*)(smem + OFF_ROW);   // [row]
    uint64_t* mb    = (uint64_t*)(smem + OFF_MBAR); // full0, full1, empty0, empty1

    const int tid = threadIdx.x;
    const int bid = blockIdx.x;
    const uint32_t full_a[2]  = { smem_u32(&mb[0]), smem_u32(&mb[1]) };
    const uint32_t empty_a[2] = { smem_u32(&mb[2]), smem_u32(&mb[3]) };
    const uint32_t td[2]      = { smem_u32(tiles[0]), smem_u32(tiles[1]) };

    const int ntiles = (NTILES - 1 - bid) / GRID + 1;  // tiles for this block

    if (tid == 0) {
#pragma unroll
        for (int s = 0; s < 2; s++) {
            asm volatile("mbarrier.init.shared.b64 [%0], 1;" :: "r"(full_a[s])  : "memory");
            asm volatile("mbarrier.init.shared.b64 [%0], 1;" :: "r"(empty_a[s]) : "memory");
        }
    }
    __syncthreads();

    if (tid >= NCONS) {
        // ================= PRODUCER (warp 8, single thread) =================
        if (tid == NCONS) {
            int ps = 0, pp = 1;   // producer cursor: phase=1 -> first 2 empty-waits pass
            for (int j = 0; j < ntiles; j++) {
                mbar_wait(empty_a[ps], pp);
                asm volatile("mbarrier.arrive.expect_tx.shared.b64 _, [%0], %1;"
                             :: "r"(full_a[ps]), "r"((uint32_t)TILE_BYTES) : "memory");
                const char* src = (const char*)F + (size_t)(bid + j * GRID) * TILE_BYTES;
                asm volatile(
                    "cp.async.bulk.shared::cluster.global.mbarrier::complete_tx::bytes "
                    "[%0], [%1], %2, [%3];"
                    :: "r"(td[ps]), "l"(src), "r"((uint32_t)TILE_BYTES), "r"(full_a[ps])
                    : "memory");
                if (++ps == 2) { ps = 0; pp ^= 1; }
            }
        }
        return;  // producer warp done after issuing all copies
    }

    // ==================== CONSUMERS (warps 0-7, 256 threads) ====================
    cudaGridDependencySynchronize();   // g_col ready (HW wait, no spin)

    int cs = 0, cp = 0;                // consumer cursor
    for (int j = 0; j < ntiles; j++) {
        const int t  = bid + j * GRID;
        const int b  = t / BLKS_PER_B;
        const int c0 = (t % BLKS_PER_B) * IMGS;

        // Stage col[b] (L2-hot) while this tile's copy may still be in flight.
        {
            const float* cptr = g_col + b * (M * R);
#pragma unroll
            for (int k = 0; k < 4; k++) {
                int idx = k * NCONS + tid;
                if (idx < M * R) col_s[idx] = cptr[idx];
            }
        }

        // Wait for tile data (acquire orders async-proxy writes before LDS).
        mbar_wait(full_a[cs], cp);

        // Row sums: thread t<224 sums row t (7 x LDS.128, conflict-free).
        if (tid < ROWS) {
            const float4* rp = reinterpret_cast<const float4*>(tiles[cs]) + tid * (R / 4);
            float s = 0.0f;
#pragma unroll
            for (int k = 0; k < R / 4; k++) {
                float4 w = rp[k];
                s += (w.x + w.y) + (w.z + w.w);
            }
            rowsum[tid] = s;
        }
        asm volatile("bar.sync 1, %0;" :: "n"(NCONS) : "memory");  // rowsum + tile reads done

        // Free the buffer for the producer.
        if (tid == 0)
            asm volatile("mbarrier.arrive.shared.b64 _, [%0];" :: "r"(empty_a[cs]) : "memory");

        // Einsum: exactly 1 output per consumer thread; 4 partial acc chains.
        {
            const int m  = tid >> 3;        // 0..31
            const int cl = tid & 7;         // 0..7
            const float* cm = col_s + m * R;
            const float* rs = rowsum + cl * R;
            float a0 = 0.f, a1 = 0.f, a2 = 0.f, a3 = 0.f;
#pragma unroll
            for (int r = 0; r < R; r += 4) {
                a0 += cm[r + 0] * rs[r + 0];
                a1 += cm[r + 1] * rs[r + 1];
                a2 += cm[r + 2] * rs[r + 2];
                a3 += cm[r + 3] * rs[r + 3];
            }
            out[((size_t)b * M + m) * C + c0 + cl] = ((a0 + a1) + (a2 + a3)) * INV_R2;
        }
        asm volatile("bar.sync 1, %0;" :: "n"(NCONS) : "memory");  // einsum reads done

        if (++cs == 2) { cs = 0; cp ^= 1; }
    }
}

extern "C" void kernel_launch(void* const* d_in, const int* in_sizes, int n_in,
                              void* d_out, int out_size) {
    const float* F  = (const float*)d_in[0];  // (B, C, R, R)
    const float* Mk = (const float*)d_in[1];  // (B, M, R, R)
    float* out = (float*)d_out;               // (B, M, C)

    static int attr_set = 0;
    if (!attr_set) {
        cudaFuncSetAttribute(persistent_fused_kernel,
                             cudaFuncAttributeMaxDynamicSharedMemorySize, SMEM_TOTAL);
        attr_set = 1;
    }

    // Primary: plain launch on the capture stream.
    {
        int n = B * M * R;  // 28672
        reduce_M_kernel<<<(n + 255) / 256, 256>>>(Mk);
    }

    // Secondary: PDL launch — starts as soon as the primary triggers.
    {
        cudaLaunchConfig_t cfg = {};
        cfg.gridDim  = dim3(GRID);
        cfg.blockDim = dim3(THREADS);
        cfg.dynamicSmemBytes = SMEM_TOTAL;
        cfg.stream = 0;
        cudaLaunchAttribute attr[1];
        attr[0].id = cudaLaunchAttributeProgrammaticStreamSerialization;
        attr[0].val.programmaticStreamSerializationAllowed = 1;
        cfg.attrs = attr;
        cfg.numAttrs = 1;
        cudaLaunchKernelEx(&cfg, persistent_fused_kernel, F, out);
    }
}

// round 16
// speedup vs baseline: 1.0013x; 1.0013x over previous
#include <cuda_runtime.h>
#include <cstdint>

#define B 32
#define M 32
#define C 1024
#define R 28
#define INV_R2 (1.0f / (R * R))

#define IMGS 4
#define ROWS (IMGS * R)                  // 112
#define TILE_FLOATS (ROWS * R)           // 3136
#define TILE_BYTES (TILE_FLOATS * 4)     // 12544
#define THREADS 128
#define BLKS_PER_B (C / IMGS)            // 256
#define NTILES (B * C / IMGS)            // 8192
#define GRID 592                         // 4 blocks/SM x 148
#define DEPTH 4

// Dynamic smem layout (bytes)
#define OFF_T     0                      // 4 tiles: 4*12544 = 50176
#define OFF_COL   (DEPTH * TILE_BYTES)   // 50176 : col_s, 896 floats
#define OFF_ROW   (OFF_COL + 3584)       // 53760 : rowsum, 112 floats
#define OFF_MBAR  (OFF_ROW + 448)        // 54208 : 4 x u64
#define SMEM_TOTAL (OFF_MBAR + 32)       // 54240 -> 4 blocks/SM

__device__ float g_col[B * M * R];

__device__ __forceinline__ uint32_t smem_u32(const void* p) {
    uint32_t a;
    asm("{ .reg .u64 t; cvta.to.shared.u64 t, %1; cvt.u32.u64 %0, t; }"
        : "=r"(a) : "l"(p));
    return a;
}

__device__ __forceinline__ void mbar_wait(uint32_t mbar_a, uint32_t parity) {
    uint32_t done;
    asm volatile(
        "{\n\t.reg .pred p;\n\t"
        "mbarrier.try_wait.parity.acquire.cta.shared::cta.b64 p, [%1], %2;\n\t"
        "selp.b32 %0, 1, 0, p;\n\t}"
        : "=r"(done) : "r"(mbar_a), "r"(parity) : "memory");
    if (!done) {
        asm volatile(
            "{\n\t.reg .pred P1;\n\t"
            "WL_%=:\n\t"
            "mbarrier.try_wait.parity.acquire.cta.shared::cta.b64 P1, [%0], %1, 0x989680;\n\t"
            "@P1 bra.uni WD_%=;\n\t"
            "bra.uni WL_%=;\n\t"
            "WD_%=:\n\t}"
            :: "r"(mbar_a), "r"(parity) : "memory");
    }
}

// ---------------------------------------------------------------------------
// Kernel 1 (primary): col[b,m,j] = sum_i Masks[b,m,i,j]. PDL-trigger first.
// ---------------------------------------------------------------------------
__global__ void reduce_M_kernel(const float* __restrict__ Mk) {
    cudaTriggerProgrammaticLaunchCompletion();
    int tid = blockIdx.x * blockDim.x + threadIdx.x;
    if (tid >= B * M * R) return;
    int j  = tid % R;
    int bm = tid / R;
    const float* p = Mk + (size_t)bm * R * R + j;
    float s = 0.0f;
#pragma unroll
    for (int i = 0; i < R; i++) s += __ldcs(p + i * R);
    g_col[tid] = s;
}

// ---------------------------------------------------------------------------
// Kernel 2 (secondary, PDL): PERSISTENT + DEPTH-4 TMA RING (R14 structure,
// smaller tiles, deeper queue). Per block: up to 4 x 12544B copies queued at
// the TMA engine; consumer-iteration jitter no longer drains the pipeline.
// Per SM: 4 blocks x 4 buffers = 200KB potentially in flight.
// Copy for tile j+3 is issued at the top of iter j — after the barrier that
// closed iter j-1, the last reader of buffer (j+3)&3 -> reuse-safe.
// Parity (j>>2)&1: each buffer's mbarrier completes once per 4 iterations.
// ---------------------------------------------------------------------------
__global__ void __launch_bounds__(THREADS)
persistent_fused_kernel(const float* __restrict__ F, float* __restrict__ out) {
    extern __shared__ char smem[];
    float* col_s  = (float*)(smem + OFF_COL);   // [m*28 + r]
    float* rowsum = (float*)(smem + OFF_ROW);   // [row], 112
    uint64_t* mb  = (uint64_t*)(smem + OFF_MBAR);

    const int tid = threadIdx.x;
    const int bid = blockIdx.x;

    uint32_t mba[DEPTH], tda[DEPTH];
#pragma unroll
    for (int s = 0; s < DEPTH; s++) {
        mba[s] = smem_u32(&mb[s]);
        tda[s] = smem_u32(smem + OFF_T + s * TILE_BYTES);
    }

    const int ntiles = (bid < NTILES) ? ((NTILES - 1 - bid) / GRID + 1) : 0;

    if (tid == 0) {
#pragma unroll
        for (int s = 0; s < DEPTH; s++)
            asm volatile("mbarrier.init.shared.b64 [%0], 1;" :: "r"(mba[s]) : "memory");
    }
    __syncthreads();

    // Prologue: queue up to DEPTH-1 copies.
    if (tid == 0) {
        int npre = ntiles < (DEPTH - 1) ? ntiles : (DEPTH - 1);
        for (int d = 0; d < npre; d++) {
            asm volatile("mbarrier.arrive.expect_tx.shared.b64 _, [%0], %1;"
                         :: "r"(mba[d]), "r"((uint32_t)TILE_BYTES) : "memory");
            asm volatile(
                "cp.async.bulk.shared::cluster.global.mbarrier::complete_tx::bytes "
                "[%0], [%1], %2, [%3];"
                :: "r"(tda[d]),
                   "l"((const char*)F + (size_t)(bid + d * GRID) * TILE_BYTES),
                   "r"((uint32_t)TILE_BYTES), "r"(mba[d]) : "memory");
        }
    }

    // HW wait for reduce_M before any g_col read.
    cudaGridDependencySynchronize();

    for (int j = 0; j < ntiles; j++) {
        const int s = j & (DEPTH - 1);
        const uint32_t parity = (j >> 2) & 1;

        // Queue copy for tile j+3 into buffer (j+3)&3 (last read in iter j-1).
        const int jn = j + DEPTH - 1;
        if (jn < ntiles && tid == 0) {
            const int ns = jn & (DEPTH - 1);
            asm volatile("mbarrier.arrive.expect_tx.shared.b64 _, [%0], %1;"
                         :: "r"(mba[ns]), "r"((uint32_t)TILE_BYTES) : "memory");
            asm volatile(
                "cp.async.bulk.shared::cluster.global.mbarrier::complete_tx::bytes "
                "[%0], [%1], %2, [%3];"
                :: "r"(tda[ns]),
                   "l"((const char*)F + (size_t)(bid + jn * GRID) * TILE_BYTES),
                   "r"((uint32_t)TILE_BYTES), "r"(mba[ns]) : "memory");
        }

        const int t  = bid + j * GRID;
        const int b  = t / BLKS_PER_B;
        const int c0 = (t % BLKS_PER_B) * IMGS;

        // Stage col[b] (L2-hot), 7 floats/thread; hidden under copy wait.
        {
            const float* cptr = g_col + b * (M * R);
#pragma unroll
            for (int k = 0; k < 7; k++)
                col_s[k * THREADS + tid] = cptr[k * THREADS + tid];
        }

        // Wait for tile data (acquire orders async-proxy writes before LDS).
        mbar_wait(mba[s], parity);

        // Row sums: thread tid<112 sums row tid (7 x LDS.128; f4-bank-group
        // 7t mod 8 permutation -> conflict-free).
        if (tid < ROWS) {
            const float4* rp = (const float4*)(smem + OFF_T + s * TILE_BYTES)
                             + tid * (R / 4);
            float sum = 0.0f;
#pragma unroll
            for (int k = 0; k < R / 4; k++) {
                float4 w = rp[k];
                sum += (w.x + w.y) + (w.z + w.w);
            }
            rowsum[tid] = sum;
        }
        __syncthreads();   // rowsum + col_s visible; tile[s] reads complete

        // Einsum: exactly 1 output/thread (m = tid/4, cl = tid%4).
        // col_s reads: 8 distinct banks/warp, broadcast x4 -> conflict-free.
        {
            const int m  = tid >> 2;
            const int cl = tid & 3;
            const float* cm = col_s + m * R;
            const float* rs = rowsum + cl * R;
            float a0 = 0.f, a1 = 0.f, a2 = 0.f, a3 = 0.f;
#pragma unroll
            for (int r = 0; r < R; r += 4) {
                a0 += cm[r + 0] * rs[r + 0];
                a1 += cm[r + 1] * rs[r + 1];
                a2 += cm[r + 2] * rs[r + 2];
                a3 += cm[r + 3] * rs[r + 3];
            }
            out[((size_t)b * M + m) * C + c0 + cl] = ((a0 + a1) + (a2 + a3)) * INV_R2;
        }
        __syncthreads();   // einsum's col_s/rowsum reads done before reuse
    }
}

extern "C" void kernel_launch(void* const* d_in, const int* in_sizes, int n_in,
                              void* d_out, int out_size) {
    const float* F  = (const float*)d_in[0];  // (B, C, R, R)
    const float* Mk = (const float*)d_in[1];  // (B, M, R, R)
    float* out = (float*)d_out;               // (B, M, C)

    static int attr_set = 0;
    if (!attr_set) {
        cudaFuncSetAttribute(persistent_fused_kernel,
                             cudaFuncAttributeMaxDynamicSharedMemorySize, SMEM_TOTAL);
        attr_set = 1;
    }

    // Primary: plain launch on the capture stream.
    {
        int n = B * M * R;  // 28672
        reduce_M_kernel<<<(n + 255) / 256, 256>>>(Mk);
    }

    // Secondary: PDL launch — starts as soon as the primary triggers.
    {
        cudaLaunchConfig_t cfg = {};
        cfg.gridDim  = dim3(GRID);
        cfg.blockDim = dim3(THREADS);
        cfg.dynamicSmemBytes = SMEM_TOTAL;
        cfg.stream = 0;
        cudaLaunchAttribute attr[1];
        attr[0].id = cudaLaunchAttributeProgrammaticStreamSerialization;
        attr[0].val.programmaticStreamSerializationAllowed = 1;
        cfg.attrs = attr;
        cfg.numAttrs = 1;
        cudaLaunchKernelEx(&cfg, persistent_fused_kernel, F, out);
    }
}

// round 17
// speedup vs baseline: 1.1807x; 1.1792x over previous
#include <cuda_runtime.h>
#include <cstdint>

#define B 32
#define M 32
#define C 1024
#define R 28
#define INV_R2 (1.0f / (R * R))

#define IMGS 8
#define ROWS (IMGS * R)                  // 224
#define TILE_FLOATS (ROWS * R)           // 6272
#define TILE_BYTES (TILE_FLOATS * 4)     // 25088
#define THREADS 256
#define BLKS_PER_B (C / IMGS)            // 128
#define NTILES (B * C / IMGS)            // 4096
#define GRID 592                         // 4 blocks/SM x 148 (proven in R14)

// Dynamic smem layout (bytes)
#define OFF_T0   0
#define OFF_T1   TILE_BYTES              // 25088
#define OFF_COL  (2 * TILE_BYTES)        // 50176 : col_s, 896 floats
#define OFF_ROW  (OFF_COL + 3584)        // 53760 : rowsum, 224 floats
#define OFF_MBAR (OFF_ROW + 896)         // 54656 : 2 x u64 mbarriers
#define SMEM_TOTAL (OFF_MBAR + 16)       // 54672 -> 4 blocks/SM

__device__ float g_col[B * M * R];

__device__ __forceinline__ uint32_t smem_u32(const void* p) {
    uint32_t a;
    asm("{ .reg .u64 t; cvta.to.shared.u64 t, %1; cvt.u32.u64 %0, t; }"
        : "=r"(a) : "l"(p));
    return a;
}

__device__ __forceinline__ void mbar_wait(uint32_t mbar_a, uint32_t parity) {
    uint32_t done;
    asm volatile(
        "{\n\t.reg .pred p;\n\t"
        "mbarrier.try_wait.parity.acquire.cta.shared::cta.b64 p, [%1], %2;\n\t"
        "selp.b32 %0, 1, 0, p;\n\t}"
        : "=r"(done) : "r"(mbar_a), "r"(parity) : "memory");
    if (!done) {
        asm volatile(
            "{\n\t.reg .pred P1;\n\t"
            "WL_%=:\n\t"
            "mbarrier.try_wait.parity.acquire.cta.shared::cta.b64 P1, [%0], %1, 0x989680;\n\t"
            "@P1 bra.uni WD_%=;\n\t"
            "bra.uni WL_%=;\n\t"
            "WD_%=:\n\t}"
            :: "r"(mbar_a), "r"(parity) : "memory");
    }
}

// ---------------------------------------------------------------------------
// Kernel 1 (primary): col[b,m,j] = sum_i Masks[b,m,i,j]. PDL-trigger first;
// fully hidden behind the fused kernel's first tiles.
// ---------------------------------------------------------------------------
__global__ void reduce_M_kernel(const float* __restrict__ Mk) {
    cudaTriggerProgrammaticLaunchCompletion();
    int tid = blockIdx.x * blockDim.x + threadIdx.x;
    if (tid >= B * M * R) return;
    int j  = tid % R;
    int bm = tid / R;
    const float* p = Mk + (size_t)bm * R * R + j;
    float s = 0.0f;
#pragma unroll
    for (int i = 0; i < R; i++) s += __ldcs(p + i * R);
    g_col[tid] = s;
}

// ---------------------------------------------------------------------------
// Kernel 2 (secondary, PDL): R14's PERSISTENT + TMA DOUBLE-BUFFER, with the
// consumer loop rebalanced: 256 threads -> einsum is exactly 1 output/thread
// (R14's 224 threads covered 256 outputs, doubling the tail for 32 threads),
// 4-way split accumulator chains, rowsum on tid<224 (identical proven
// conflict-free 7xLDS.128 pattern). Pipeline structure byte-identical to R14.
// ---------------------------------------------------------------------------
__global__ void __launch_bounds__(THREADS)
persistent_fused_kernel(const float* __restrict__ F, float* __restrict__ out) {
    extern __shared__ char smem[];
    float* tiles[2] = { (float*)(smem + OFF_T0), (float*)(smem + OFF_T1) };
    float* col_s    = (float*)(smem + OFF_COL);   // [m*28 + r]
    float* rowsum   = (float*)(smem + OFF_ROW);   // [c_local*28 + i]
    uint64_t* mbar  = (uint64_t*)(smem + OFF_MBAR);

    const int tid = threadIdx.x;
    const int bid = blockIdx.x;
    const uint32_t mb[2] = { smem_u32(&mbar[0]), smem_u32(&mbar[1]) };
    const uint32_t td[2] = { smem_u32(tiles[0]), smem_u32(tiles[1]) };

    if (tid == 0) {
        asm volatile("mbarrier.init.shared.b64 [%0], 1;" :: "r"(mb[0]) : "memory");
        asm volatile("mbarrier.init.shared.b64 [%0], 1;" :: "r"(mb[1]) : "memory");
    }
    __syncthreads();

    // Prologue: copy for first tile into buf 0.
    if (bid < NTILES && tid == 0) {
        asm volatile("mbarrier.arrive.expect_tx.shared.b64 _, [%0], %1;"
                     :: "r"(mb[0]), "r"((uint32_t)TILE_BYTES) : "memory");
        asm volatile(
            "cp.async.bulk.shared::cluster.global.mbarrier::complete_tx::bytes "
            "[%0], [%1], %2, [%3];"
            :: "r"(td[0]), "l"((const char*)F + (size_t)bid * TILE_BYTES),
               "r"((uint32_t)TILE_BYTES), "r"(mb[0]) : "memory");
    }

    // HW wait for reduce_M before any g_col read.
    cudaGridDependencySynchronize();

    int it = 0;
    for (int t = bid; t < NTILES; t += GRID, ++it) {
        const int stage = it & 1;
        const uint32_t parity = (it >> 1) & 1;

        // Prefetch tile t+GRID into the alternate buffer (in flight during
        // this tile's wait + compute). Reuse-safe: that buffer's last reads
        // were closed by the final __syncthreads of iteration it-1.
        const int tn = t + GRID;
        if (tn < NTILES && tid == 0) {
            const int ns = stage ^ 1;
            asm volatile("mbarrier.arrive.expect_tx.shared.b64 _, [%0], %1;"
                         :: "r"(mb[ns]), "r"((uint32_t)TILE_BYTES) : "memory");
            asm volatile(
                "cp.async.bulk.shared::cluster.global.mbarrier::complete_tx::bytes "
                "[%0], [%1], %2, [%3];"
                :: "r"(td[ns]), "l"((const char*)F + (size_t)tn * TILE_BYTES),
                   "r"((uint32_t)TILE_BYTES), "r"(mb[ns]) : "memory");
        }

        const int b  = t / BLKS_PER_B;
        const int c0 = (t % BLKS_PER_B) * IMGS;

        // Stage col[b] (L2-hot; hidden under the copy wait).
        {
            const float* cp = g_col + b * (M * R);
#pragma unroll
            for (int k = 0; k < 4; k++) {
                int idx = k * THREADS + tid;
                if (idx < M * R) col_s[idx] = cp[idx];
            }
        }

        // Wait for this tile's data (acquire orders async-proxy writes).
        mbar_wait(mb[stage], parity);

        // Row sums: thread tid<224 sums row tid (7 x LDS.128; f4-bank-group
        // 7t mod 8 is a permutation per 8-lane phase -> conflict-free).
        if (tid < ROWS) {
            const float4* rp = reinterpret_cast<const float4*>(tiles[stage]) + tid * (R / 4);
            float s = 0.0f;
#pragma unroll
            for (int k = 0; k < R / 4; k++) {
                float4 w = rp[k];
                s += (w.x + w.y) + (w.z + w.w);
            }
            rowsum[tid] = s;
        }
        __syncthreads();   // rowsum + col_s visible; tile[stage] reads done

        // Einsum: exactly 1 output/thread (m = tid/8, cl = tid%8);
        // 4 parallel accumulator chains (7x4 instead of 28 serial FMAs).
        {
            const int m  = tid >> 3;
            const int cl = tid & 7;
            const float* cm = col_s + m * R;
            const float* rs = rowsum + cl * R;
            float a0 = 0.f, a1 = 0.f, a2 = 0.f, a3 = 0.f;
#pragma unroll
            for (int r = 0; r < R; r += 4) {
                a0 += cm[r + 0] * rs[r + 0];
                a1 += cm[r + 1] * rs[r + 1];
                a2 += cm[r + 2] * rs[r + 2];
                a3 += cm[r + 3] * rs[r + 3];
            }
            out[((size_t)b * M + m) * C + c0 + cl] = ((a0 + a1) + (a2 + a3)) * INV_R2;
        }
        __syncthreads();   // einsum's col_s/rowsum reads done before reuse
    }
}

extern "C" void kernel_launch(void* const* d_in, const int* in_sizes, int n_in,
                              void* d_out, int out_size) {
    const float* F  = (const float*)d_in[0];  // (B, C, R, R)
    const float* Mk = (const float*)d_in[1];  // (B, M, R, R)
    float* out = (float*)d_out;               // (B, M, C)

    static int attr_set = 0;
    if (!attr_set) {
        cudaFuncSetAttribute(persistent_fused_kernel,
                             cudaFuncAttributeMaxDynamicSharedMemorySize, SMEM_TOTAL);
        attr_set = 1;
    }

    // Primary: plain launch on the capture stream.
    {
        int n = B * M * R;  // 28672
        reduce_M_kernel<<<(n + 255) / 256, 256>>>(Mk);
    }

    // Secondary: PDL launch — starts as soon as the primary triggers.
    {
        cudaLaunchConfig_t cfg = {};
        cfg.gridDim  = dim3(GRID);
        cfg.blockDim = dim3(THREADS);
        cfg.dynamicSmemBytes = SMEM_TOTAL;
        cfg.stream = 0;
        cudaLaunchAttribute attr[1];
        attr[0].id = cudaLaunchAttributeProgrammaticStreamSerialization;
        attr[0].val.programmaticStreamSerializationAllowed = 1;
        cfg.attrs = attr;
        cfg.numAttrs = 1;
        cudaLaunchKernelEx(&cfg, persistent_fused_kernel, F, out);
    }
}